// round 17
// baseline (speedup 1.0000x reference)
#include <cuda_runtime.h>

#define NN 256
#define BB 64
#define FBIG 1e8f
#define K2   144.269504089f     // (1/gamma)*log2(e), gamma = 0.01
#define GLN2 0.006931471806f    // gamma*ln(2)
#define TT   320
#define FULL 0xffffffffu

// Softmin-weight scratch, time-major (R13 layout): per (iter t, group V4):
// p[0]=(wu0,wl0,wu1,wl1), p[1]=(wu2,wl2,wu3,wl3) for rows 4*V4+1..4*V4+4,
// column q = t - V4 + 1. wd = 1-wu-wl. 42 MB -> L2-resident.
__device__ float4 g_W[BB * TT * 64 * 2];
__device__ float g_partV[BB];
__device__ float g_partE[BB];
__device__ unsigned g_ticket = 0;

__device__ __forceinline__ float ex2(float x){ float r; asm("ex2.approx.f32 %0,%1;":"=f"(r):"f"(x)); return r; }
__device__ __forceinline__ float lg2(float x){ float r; asm("lg2.approx.f32 %0,%1;":"=f"(r):"f"(x)); return r; }
__device__ __forceinline__ float rcpa(float x){ float r; asm("rcp.approx.f32 %0,%1;":"=f"(r):"f"(x)); return r; }

__global__ __launch_bounds__(64, 1) void dilate_fb_kernel(
    const float* __restrict__ y_pred,
    const float* __restrict__ y_true,
    float* __restrict__ out)
{
    __shared__ float s_o2[384];             // zero-padded o: real data at [63, 319)
    __shared__ float s_t[NN];
    __shared__ float s_fm[2], s_fw[2];      // fwd cross-warp handoff, parity
    __shared__ float s_vnn;
    __shared__ int   s_last;

    const int b   = blockIdx.x;
    const int tid = threadIdx.x;      // fwd virtual lane V; owns rows 4V+1..4V+4
    const int w   = tid >> 5;
    const int l   = tid & 31;

    for (int x = tid; x < 384; x += 64) {
        s_o2[x] = (x >= 63 && x < 63 + NN) ? y_pred[b * NN + (x - 63)] : 0.0f;
    }
    for (int x = tid; x < NN; x += 64) {
        s_t[x] = y_true[b * NN + x];
    }
    __syncthreads();

    const float ti0 = s_t[4 * tid];
    const float ti1 = s_t[4 * tid + 1];
    const float ti2 = s_t[4 * tid + 2];
    const float ti3 = s_t[4 * tid + 3];
    float4* __restrict__ Wb = g_W + (size_t)b * (TT * 64 * 2);

    // ===== FORWARD (R13 semantics): (m,w) soft-min, 4 rows/lane, 2-warp ladder ==
    {
        float mm0 = FBIG, mm1 = FBIG, mm2 = FBIG, mm3 = FBIG;
        float ww0 = 1.0f, ww1 = 1.0f, ww2 = 1.0f, ww3 = 1.0f;
        float shAm = FBIG, shAw = 1.0f, shBm = FBIG, shBw = 1.0f;
        float lzum = FBIG, lzuw = 1.0f, lzdm = FBIG, lzdw = 1.0f;

        for (int c = 0; c < TT / 8; ++c) {
            float o_pre[8];
            #pragma unroll
            for (int k = 0; k < 8; ++k)
                o_pre[k] = s_o2[63 + c * 8 + k - tid];   // padded: no clamps
            #pragma unroll
            for (int k = 0; k < 8; ++k) {
                const int t = c * 8 + k;
                const bool act   = (unsigned)(t - tid) < NN;
                const bool first = (t == tid);
                if (first) { mm0 = FBIG; mm1 = FBIG; mm2 = FBIG; mm3 = FBIG;
                             ww0 = 1.0f; ww1 = 1.0f; ww2 = 1.0f; ww3 = 1.0f; }
                float um, uw, dm, dw;
                if (l == 0) { um = (w == 0) ? FBIG : lzum; uw = (w == 0) ? 1.0f : lzuw;
                              dm = (w == 0) ? FBIG : lzdm; dw = (w == 0) ? 1.0f : lzdw; }
                else        { um = shAm; uw = shAw; dm = shBm; dw = shBw; }
                if (first) { dm = (tid == 0) ? 0.0f : FBIG; dw = 1.0f; }   // V[0][0]=0
                const float oj = o_pre[k];
                float wu_s0, wl_s0, wu_s1, wl_s1, wu_s2, wl_s2, wu_s3, wl_s3;
                // row0
                {
                    float ms = fminf(mm0, fminf(um, dm));
                    float kk = ms * K2;
                    float tl = ww0 * ex2(fmaf(-K2, mm0, kk));
                    float tu = uw  * ex2(fmaf(-K2, um,  kk));
                    float td = dw  * ex2(fmaf(-K2, dm,  kk));
                    float nw = tl + tu + td;
                    float rc = rcpa(nw);
                    wu_s0 = tu * rc; wl_s0 = tl * rc;
                    float d = ti0 - oj;
                    float nm = fmaf(d, d, ms);
                    dm = mm0; dw = ww0;
                    mm0 = nm; ww0 = nw;
                    um = nm;  uw = nw;
                }
                // row1
                {
                    float ms = fminf(mm1, fminf(um, dm));
                    float kk = ms * K2;
                    float tl = ww1 * ex2(fmaf(-K2, mm1, kk));
                    float tu = uw  * ex2(fmaf(-K2, um,  kk));
                    float td = dw  * ex2(fmaf(-K2, dm,  kk));
                    float nw = tl + tu + td;
                    float rc = rcpa(nw);
                    wu_s1 = tu * rc; wl_s1 = tl * rc;
                    float d = ti1 - oj;
                    float nm = fmaf(d, d, ms);
                    dm = mm1; dw = ww1;
                    mm1 = nm; ww1 = nw;
                    um = nm;  uw = nw;
                }
                // row2
                {
                    float ms = fminf(mm2, fminf(um, dm));
                    float kk = ms * K2;
                    float tl = ww2 * ex2(fmaf(-K2, mm2, kk));
                    float tu = uw  * ex2(fmaf(-K2, um,  kk));
                    float td = dw  * ex2(fmaf(-K2, dm,  kk));
                    float nw = tl + tu + td;
                    float rc = rcpa(nw);
                    wu_s2 = tu * rc; wl_s2 = tl * rc;
                    float d = ti2 - oj;
                    float nm = fmaf(d, d, ms);
                    dm = mm2; dw = ww2;
                    mm2 = nm; ww2 = nw;
                    um = nm;  uw = nw;
                }
                // row3
                {
                    float ms = fminf(mm3, fminf(um, dm));
                    float kk = ms * K2;
                    float tl = ww3 * ex2(fmaf(-K2, mm3, kk));
                    float tu = uw  * ex2(fmaf(-K2, um,  kk));
                    float td = dw  * ex2(fmaf(-K2, dm,  kk));
                    float nw = tl + tu + td;
                    float rc = rcpa(nw);
                    wu_s3 = tu * rc; wl_s3 = tl * rc;
                    float d = ti3 - oj;
                    float nm = fmaf(d, d, ms);
                    mm3 = nm; ww3 = nw;
                }
                if (act) {
                    float4* p = Wb + (((t << 6) + tid) << 1);
                    p[0] = make_float4(wu_s0, wl_s0, wu_s1, wl_s1);
                    p[1] = make_float4(wu_s2, wl_s2, wu_s3, wl_s3);
                    if (tid == 63 && t == NN + 62)
                        s_vnn = fmaf(-GLN2, lg2(ww3), mm3);     // V[N][N]
                }
                float hm = act ? mm3 : FBIG;
                float hw = act ? ww3 : 1.0f;
                shBm = shAm; shBw = shAw;
                shAm = __shfl_up_sync(FULL, hm, 1);
                shAw = __shfl_up_sync(FULL, hw, 1);
                if (l == 31 && w == 0) { s_fm[t & 1] = hm; s_fw[t & 1] = hw; }
                __syncthreads();
                if (w == 1) { lzdm = lzum; lzdw = lzuw;
                              lzum = s_fm[t & 1]; lzuw = s_fw[t & 1]; }
            }
            // renormalize every 8 cols: m <- folded V, w <- 1 (bounds w)
            mm0 = fmaf(-GLN2, lg2(ww0), mm0); ww0 = 1.0f;
            mm1 = fmaf(-GLN2, lg2(ww1), mm1); ww1 = 1.0f;
            mm2 = fmaf(-GLN2, lg2(ww2), mm2); ww2 = 1.0f;
            mm3 = fmaf(-GLN2, lg2(ww3), mm3); ww3 = 1.0f;
        }
    }

    // ===== BACKWARD: single-warp weight-flow, 8 rows/lane, DUAL-STREAM =========
    // Lane l owns rows 249-8l..256-8l (r=0: i=256-8l). Iter t: column j=256-(t-l).
    // r=0..3 -> group gA=63-2l at slot 318-t-l; r=4..7 -> group gB=62-2l at slot
    // 317-t-l. Streams are independent (NO slot-sharing across groups — the R16
    // rotation bug). Both pipelined 2 iterations deep via walking pointers.
    float sumE = 0.0f;
    if (w == 0) {
        float pl[8], pdp[8];
        #pragma unroll
        for (int r = 0; r < 8; ++r) { pl[r] = 0.0f; pdp[r] = 0.0f; }
        float shApu = 0.0f, shApd = 0.0f, shBpd = 0.0f;
        const int gA = 63 - 2 * l, gB = 62 - 2 * l;
        const float4 f4z = make_float4(0, 0, 0, 0);
        float4 cA0, cA1, cB0, cB1, nA0, nA1, nB0, nB1;

        const float4* qA = Wb + ((((318 - l) * 64) + gA) << 1);   // slotA(0)
        const float4* qB = Wb + ((((317 - l) * 64) + gB) << 1);   // slotB(0)
        {   // t = 0 pair (only lane 0 active)
            bool a0 = (l == 0);
            cA0 = a0 ? __ldg(qA) : f4z;  cA1 = a0 ? __ldg(qA + 1) : f4z;
            cB0 = a0 ? __ldg(qB) : f4z;  cB1 = a0 ? __ldg(qB + 1) : f4z;
        }
        {   // t = 1 pair
            bool a1 = (l <= 1);
            const float4* rA = qA - 128;
            const float4* rB = qB - 128;
            nA0 = a1 ? __ldg(rA) : f4z;  nA1 = a1 ? __ldg(rA + 1) : f4z;
            nB0 = a1 ? __ldg(rB) : f4z;  nB1 = a1 ? __ldg(rB + 1) : f4z;
        }
        qA -= 256; qB -= 256;            // now at slot(t=2)
        float wqb = (float)(-9 * l);     // (i-j) for r=0 at t=0

        #pragma unroll 4
        for (int t = 0; t < 287; ++t) {
            // prefetch t+2 (both streams); walking pointers, predicated loads
            float4 mA0, mA1, mB0, mB1;
            {
                bool a2 = (unsigned)(t + 2 - l) < 256u;
                mA0 = a2 ? __ldg(qA) : f4z;  mA1 = a2 ? __ldg(qA + 1) : f4z;
                mB0 = a2 ? __ldg(qB) : f4z;  mB1 = a2 ? __ldg(qB + 1) : f4z;
                qA -= 128; qB -= 128;
            }
            const bool act = (unsigned)(t - l) < NN;
            float pu_in = (l == 0) ? 0.0f : shApu;   // lane l-1 pu7 @ t-1
            float pd_in = (l == 0) ? 0.0f : shBpd;   // lane l-1 pd7 @ t-2
            // row r <-> within-group component 3-(r&3)
            float wu_[8], wl_[8];
            wu_[0] = cA1.z; wl_[0] = cA1.w;  wu_[1] = cA1.x; wl_[1] = cA1.y;
            wu_[2] = cA0.z; wl_[2] = cA0.w;  wu_[3] = cA0.x; wl_[3] = cA0.y;
            wu_[4] = cB1.z; wl_[4] = cB1.w;  wu_[5] = cB1.x; wl_[5] = cB1.y;
            wu_[6] = cB0.z; wl_[6] = cB0.w;  wu_[7] = cB0.x; wl_[7] = cB0.y;
            #pragma unroll
            for (int r = 0; r < 8; ++r) {
                float E = pu_in + pl[r] + pd_in;
                if (l == 0 && t == 0 && r == 0) E = 1.0f;   // E[N][N]
                if (!act) E = 0.0f;
                float wd = 1.0f - wu_[r] - wl_[r];
                float pu = E * wu_[r], pd = E * wd, pln = E * wl_[r];
                float wq = wqb - (float)r;
                sumE = fmaf(E, wq * wq, sumE);
                pd_in = pdp[r]; pdp[r] = pd; pl[r] = pln; pu_in = pu;
            }
            float pu7 = pu_in, pd7 = pdp[7];
            shBpd = shApd;
            shApd = __shfl_up_sync(FULL, pd7, 1);
            shApu = __shfl_up_sync(FULL, pu7, 1);
            cA0 = nA0; cA1 = nA1; cB0 = nB0; cB1 = nB1;
            nA0 = mA0; nA1 = mA1; nB0 = mB0; nB1 = mB1;
            wqb += 1.0f;
        }
        // warp reduction (lane 0 ends with the total)
        #pragma unroll
        for (int off = 16; off > 0; off >>= 1)
            sumE += __shfl_down_sync(FULL, sumE, off);
    }
    __syncthreads();   // warp 1 waits here during the backward

    // ---- per-block partials + deterministic last-block finalize ----
    if (tid == 0) {
        g_partV[b] = s_vnn;
        g_partE[b] = sumE;            // tid0 = warp0 lane0 holds the reduced sum
        __threadfence();
        unsigned tk = atomicAdd(&g_ticket, 1u);
        s_last = (tk == BB - 1) ? 1 : 0;
    }
    __syncthreads();
    if (s_last && tid < 32) {
        __threadfence();
        float sv = __ldcg(&g_partV[tid]) + __ldcg(&g_partV[tid + 32]);
        float se = __ldcg(&g_partE[tid]) + __ldcg(&g_partE[tid + 32]);
        #pragma unroll
        for (int off = 16; off > 0; off >>= 1) {
            sv += __shfl_down_sync(FULL, sv, off);
            se += __shfl_down_sync(FULL, se, off);
        }
        if (tid == 0) {
            float loss_shape    = sv * (1.0f / (float)BB);
            float loss_temporal = se * (1.0f / ((float)BB * (float)(NN * NN)));
            out[0] = 0.5f * loss_shape + 0.5f * loss_temporal;
            g_ticket = 0;   // reset for graph replay
        }
    }
}

extern "C" void kernel_launch(void* const* d_in, const int* in_sizes, int n_in,
                              void* d_out, int out_size) {
    const float* y_pred = (const float*)d_in[0];
    const float* y_true = (const float*)d_in[1];
    dilate_fb_kernel<<<BB, 64>>>(y_pred, y_true, (float*)d_out);
}